// round 14
// baseline (speedup 1.0000x reference)
#include <cuda_runtime.h>
#include <cstdint>

// WeightedBCELoss: out[b,s] = (labels[b,s]==0) ? -log(1-pred) : -weight[b]*log(pred)
// pred [4096,8192] f32, labels [4096,8192] i32, weight [4096] f32.
//
// FINAL — R12 config, global optimum of the explored space:
//   ncu 51.84us, DRAM 85.7%, 6786 GB/s (vs ~6300 B/cyc LTS chip cap).
// Design (each axis isolated over 13 rounds):
//   - 16384 blocks x 256 thr; block = 512 aligned float4 inside one row
//   - uniform per-block weight broadcast (row = blk >> 2)
//   - 2 float4/thread, 4 front-batched 16B loads (MLP_p1=4; MLP8 -7%, MLP2 -5%)
//   - DEFAULT cache policy both ways (policy 2x2 measured: def/def 51.8us beats
//     cs/def 53.0, cs/cs 53.2-54.7, cs/wt 54.2 — lazy L2 writeback forms the
//     best DRAM bursts; evict-first read hints lose residual sector hits)
//   - single __logf per element via argument-select (MUFU fully hidden, fma 8.5%)
//   - persistence, 512-thr blocks, int32 indexing, L2::256B prefetch: all
//     tested, all neutral-or-worse.

#define BATCH 4096
#define SENT  8192
#define V4_PER_ROW (SENT / 4)   // 2048
#define THREADS 256

__device__ __forceinline__ float bce_term(float p, int l, float w) {
    float a = (l == 0) ? (1.0f - p) : p;
    float s = (l == 0) ? 1.0f : w;
    return -s * __logf(a);
}

__global__ __launch_bounds__(THREADS, 8)
void wbce_kernel(const float4* __restrict__ pred,
                 const int4*   __restrict__ labels,
                 const float*  __restrict__ weight,
                 float4*       __restrict__ out)
{
    // Block covers float4 range [blk*512, blk*512+512) — entirely inside one
    // row (512 | 2048). row = blk >> 2. Weight is uniform per block.
    const int   row = blockIdx.x >> 2;
    const float w   = __ldg(&weight[row]);

    const long i0 = (long)blockIdx.x * 512 + threadIdx.x;
    const long i1 = i0 + 256;

    // Front-batched: 4 independent 16B loads (MLP_p1 = 4), default policy.
    float4 p0 = pred[i0];
    float4 p1 = pred[i1];
    int4   l0 = labels[i0];
    int4   l1 = labels[i1];

    float4 o0, o1;
    o0.x = bce_term(p0.x, l0.x, w);
    o0.y = bce_term(p0.y, l0.y, w);
    o0.z = bce_term(p0.z, l0.z, w);
    o0.w = bce_term(p0.w, l0.w, w);
    o1.x = bce_term(p1.x, l1.x, w);
    o1.y = bce_term(p1.y, l1.y, w);
    o1.z = bce_term(p1.z, l1.z, w);
    o1.w = bce_term(p1.w, l1.w, w);

    out[i0] = o0;
    out[i1] = o1;
}

extern "C" void kernel_launch(void* const* d_in, const int* in_sizes, int n_in,
                              void* d_out, int out_size)
{
    const float4* pred   = (const float4*)d_in[0];
    const int4*   labels = (const int4*)d_in[1];
    const float*  weight = (const float*)d_in[2];
    float4*       out    = (float4*)d_out;

    const int total_v4 = BATCH * V4_PER_ROW;   // 8,388,608
    wbce_kernel<<<total_v4 / 512, THREADS>>>(pred, labels, weight, out);
}

// round 15
// speedup vs baseline: 1.0041x; 1.0041x over previous
#include <cuda_runtime.h>
#include <cstdint>

// WeightedBCELoss: out[b,s] = (labels[b,s]==0) ? -log(1-pred) : -weight[b]*log(pred)
// pred [4096,8192] f32, labels [4096,8192] i32, weight [4096] f32.
//
// R15 = R12 (certified: ncu 51.8-52.0us, 85.2-85.7% DRAM, def/def policy)
// with 256-bit vector memory ops (sm_100+ ld/st.global.v8.f32, SASS LDG.E.256):
// same 32 B/thread/array, half the memory instructions -> lower LSU
// dispatch-queue pressure. Traffic and coalescing identical.

#define BATCH 4096
#define SENT  8192
#define THREADS 256
// Each thread: 8 floats per array. Block: 256*8 = 2048 floats = one row... no:
// block covers 2048 floats = 1/4 row? Row = 8192 floats. Block = 2048 floats.
// 4 blocks per row -> row = blk >> 2 (same as R12). Total blocks = 16384.

struct F8 { float v[8]; };
struct I8 { int   v[8]; };

__device__ __forceinline__ F8 ldg_v8f(const float* p) {
    F8 r;
    asm volatile("ld.global.v8.f32 {%0,%1,%2,%3,%4,%5,%6,%7}, [%8];"
                 : "=f"(r.v[0]), "=f"(r.v[1]), "=f"(r.v[2]), "=f"(r.v[3]),
                   "=f"(r.v[4]), "=f"(r.v[5]), "=f"(r.v[6]), "=f"(r.v[7])
                 : "l"(p));
    return r;
}

__device__ __forceinline__ I8 ldg_v8i(const int* p) {
    I8 r;
    asm volatile("ld.global.v8.u32 {%0,%1,%2,%3,%4,%5,%6,%7}, [%8];"
                 : "=r"(r.v[0]), "=r"(r.v[1]), "=r"(r.v[2]), "=r"(r.v[3]),
                   "=r"(r.v[4]), "=r"(r.v[5]), "=r"(r.v[6]), "=r"(r.v[7])
                 : "l"(p));
    return r;
}

__device__ __forceinline__ void stg_v8f(float* p, const F8& r) {
    asm volatile("st.global.v8.f32 [%0], {%1,%2,%3,%4,%5,%6,%7,%8};"
                 :: "l"(p),
                    "f"(r.v[0]), "f"(r.v[1]), "f"(r.v[2]), "f"(r.v[3]),
                    "f"(r.v[4]), "f"(r.v[5]), "f"(r.v[6]), "f"(r.v[7])
                 : "memory");
}

__device__ __forceinline__ float bce_term(float p, int l, float w) {
    float a = (l == 0) ? (1.0f - p) : p;
    float s = (l == 0) ? 1.0f : w;
    return -s * __logf(a);
}

__global__ __launch_bounds__(THREADS, 8)
void wbce_kernel(const float* __restrict__ pred,
                 const int*   __restrict__ labels,
                 const float* __restrict__ weight,
                 float*       __restrict__ out)
{
    // Block covers 2048 consecutive floats = quarter row. row = blk >> 2.
    const int   row = blockIdx.x >> 2;
    const float w   = __ldg(&weight[row]);

    // Thread t handles floats [base, base+8); 32B aligned (t*32 bytes).
    const long base = (long)blockIdx.x * 2048 + (long)threadIdx.x * 8;

    F8 p = ldg_v8f(pred + base);
    I8 l = ldg_v8i(labels + base);

    F8 o;
    #pragma unroll
    for (int k = 0; k < 8; k++)
        o.v[k] = bce_term(p.v[k], l.v[k], w);

    stg_v8f(out + base, o);
}

extern "C" void kernel_launch(void* const* d_in, const int* in_sizes, int n_in,
                              void* d_out, int out_size)
{
    const float* pred   = (const float*)d_in[0];
    const int*   labels = (const int*)d_in[1];
    const float* weight = (const float*)d_in[2];
    float*       out    = (float*)d_out;

    const int total = BATCH * SENT;              // 33,554,432 floats
    const int blocks = total / 2048;             // 16384
    wbce_kernel<<<blocks, THREADS>>>(pred, labels, weight, out);
}